// round 7
// baseline (speedup 1.0000x reference)
#include <cuda_runtime.h>

// Problem constants (fixed by the dataset)
#define NN 50000
#define DD 64
#define EE 1250000

// Scratch (device globals: no allocation allowed). 16B-aligned for vector ld/st.
__device__ __align__(16) float g_dis[NN];        // deg^{-1/2}
__device__ __align__(16) float g_h[NN * DD];     // post-GEMM features
__device__ __align__(16) float g_agg[NN * DD];   // aggregation buffer
__device__ __align__(16) int   g_deg[NN];        // in-degree counts
__device__ __align__(16) int   g_off[NN + 1];    // CSR offsets
__device__ __align__(16) int   g_cur[NN];        // placement cursors
__device__ __align__(16) int   g_src[EE];        // CSR source node per slot
__device__ __align__(16) float g_enorm[EE];      // CSR edge norm per slot

// ---------------------------------------------------------------------------
// Pass 1: init degree accumulators
// ---------------------------------------------------------------------------
__global__ void init_k() {
    int i = blockIdx.x * blockDim.x + threadIdx.x;
    if (i < NN) {
        g_dis[i] = 2.0f;  // improved=True self-loop fill contributes to deg
        g_deg[i] = 0;
    }
}

// Pass 2: per-target-node histogram (count + weighted degree)
__global__ void count_k(const int* __restrict__ cols,
                        const float* __restrict__ w) {
    int e = blockIdx.x * blockDim.x + threadIdx.x;
    if (e < EE) {
        unsigned c = (unsigned)cols[e];
        if (c < NN) {
            atomicAdd(&g_deg[c], 1);
            atomicAdd(&g_dis[c], w[e]);
        }
    }
}

// Pass 3: single-block exclusive scan of g_deg -> g_off, g_cur
__global__ void scan_k() {
    __shared__ int partial[1024];
    const int CH = (NN + 1023) / 1024;  // 49
    int t = threadIdx.x;
    int base = t * CH;
    int sum = 0;
    for (int i = 0; i < CH; i++) {
        int idx = base + i;
        if (idx < NN) sum += g_deg[idx];
    }
    partial[t] = sum;
    __syncthreads();
    // Hillis-Steele inclusive scan over 1024 partials
    for (int off = 1; off < 1024; off <<= 1) {
        int v = (t >= off) ? partial[t - off] : 0;
        __syncthreads();
        partial[t] += v;
        __syncthreads();
    }
    int run = (t > 0) ? partial[t - 1] : 0;  // exclusive start for this chunk
    for (int i = 0; i < CH; i++) {
        int idx = base + i;
        if (idx < NN) {
            g_off[idx] = run;
            g_cur[idx] = run;
            run += g_deg[idx];
        }
    }
    if (t == 1023) g_off[NN] = partial[1023];
}

// Pass 4: deg -> deg^{-1/2}
__global__ void rsqrt_k() {
    int i = blockIdx.x * blockDim.x + threadIdx.x;
    if (i < NN) {
        float d = g_dis[i];
        g_dis[i] = (d > 0.0f) ? rsqrtf(d) : 0.0f;
    }
}

// Pass 5: fill CSR slots (src node + precomputed edge norm)
__global__ void fill_k(const int* __restrict__ rows,
                       const int* __restrict__ cols,
                       const float* __restrict__ w) {
    int e = blockIdx.x * blockDim.x + threadIdx.x;
    if (e < EE) {
        unsigned r = (unsigned)rows[e];
        unsigned c = (unsigned)cols[e];
        if (r < NN && c < NN) {
            int pos = atomicAdd(&g_cur[c], 1);
            g_src[pos] = (int)r;
            g_enorm[pos] = g_dis[r] * w[e] * g_dis[c];
        }
    }
}

// ---------------------------------------------------------------------------
// GEMM: g_h[32-row tile] = act(X) @ W,  act = (bias? relu(x+bias) : x)
// blockDim = 128; each thread computes a 4x4 output micro-tile.
// X == nullptr means "read g_agg" (device symbol input).
// ---------------------------------------------------------------------------
__global__ __launch_bounds__(128) void gemm_k(const float* __restrict__ X,
                                              const float* __restrict__ W,
                                              const float* __restrict__ bias) {
    __shared__ float Ws[64][65];
    __shared__ float Xs[32][65];
    int tx = threadIdx.x;
    int row0 = blockIdx.x * 32;
    const float* __restrict__ src = X ? X : (const float*)g_agg;

    // load W (64x64) cooperatively, float4
    for (int i = tx; i < 64 * 16; i += 128) {
        int k = i >> 4, c4 = (i & 15) * 4;
        float4 v = *(const float4*)(W + k * 64 + c4);
        Ws[k][c4] = v.x; Ws[k][c4 + 1] = v.y; Ws[k][c4 + 2] = v.z; Ws[k][c4 + 3] = v.w;
    }
    // load X tile with fused bias+relu
    for (int i = tx; i < 32 * 16; i += 128) {
        int r = i >> 4, c4 = (i & 15) * 4;
        int gr = row0 + r;
        float4 v = make_float4(0.f, 0.f, 0.f, 0.f);
        if (gr < NN) v = *(const float4*)(src + (size_t)gr * 64 + c4);
        if (bias) {
            v.x = fmaxf(v.x + bias[c4], 0.f);
            v.y = fmaxf(v.y + bias[c4 + 1], 0.f);
            v.z = fmaxf(v.z + bias[c4 + 2], 0.f);
            v.w = fmaxf(v.w + bias[c4 + 3], 0.f);
        }
        Xs[r][c4] = v.x; Xs[r][c4 + 1] = v.y; Xs[r][c4 + 2] = v.z; Xs[r][c4 + 3] = v.w;
    }
    __syncthreads();

    int rB = (tx >> 4) * 4;   // 0..28
    int cB = (tx & 15) * 4;   // 0..60
    float acc[4][4] = {};
#pragma unroll
    for (int k = 0; k < 64; k++) {
        float xv[4], wv[4];
#pragma unroll
        for (int i = 0; i < 4; i++) xv[i] = Xs[rB + i][k];
#pragma unroll
        for (int j = 0; j < 4; j++) wv[j] = Ws[k][cB + j];
#pragma unroll
        for (int i = 0; i < 4; i++)
#pragma unroll
            for (int j = 0; j < 4; j++) acc[i][j] = fmaf(xv[i], wv[j], acc[i][j]);
    }
#pragma unroll
    for (int i = 0; i < 4; i++) {
        int gr = row0 + rB + i;
        if (gr < NN) {
            float4 v = make_float4(acc[i][0], acc[i][1], acc[i][2], acc[i][3]);
            *(float4*)(g_h + (size_t)gr * 64 + cB) = v;
        }
    }
}

// ---------------------------------------------------------------------------
// Aggregation gather: warp per target node, 2 dims per lane.
//   agg[n,:] = 2*dis[n]^2 * h[n,:] + sum_{j in CSR[n]} enorm[j] * h[src[j],:]
// No atomics; deterministic per CSR order.
// ---------------------------------------------------------------------------
__global__ __launch_bounds__(256) void gather_k() {
    int warp = (blockIdx.x * blockDim.x + threadIdx.x) >> 5;
    int lane = threadIdx.x & 31;
    if (warp >= NN) return;
    int beg = g_off[warp];
    int end = g_off[warp + 1];
    float s = g_dis[warp];
    float self = 2.0f * s * s;
    float2 h0 = *(const float2*)(g_h + (size_t)warp * 64 + lane * 2);
    float ax = h0.x * self, ay = h0.y * self;

    int j = beg;
    // unroll-by-2 to expose MLP
    for (; j + 1 < end; j += 2) {
        int s0 = g_src[j], s1 = g_src[j + 1];
        float w0 = g_enorm[j], w1 = g_enorm[j + 1];
        float2 v0 = *(const float2*)(g_h + (size_t)s0 * 64 + lane * 2);
        float2 v1 = *(const float2*)(g_h + (size_t)s1 * 64 + lane * 2);
        ax = fmaf(w0, v0.x, ax); ay = fmaf(w0, v0.y, ay);
        ax = fmaf(w1, v1.x, ax); ay = fmaf(w1, v1.y, ay);
    }
    if (j < end) {
        int s0 = g_src[j];
        float w0 = g_enorm[j];
        float2 v0 = *(const float2*)(g_h + (size_t)s0 * 64 + lane * 2);
        ax = fmaf(w0, v0.x, ax); ay = fmaf(w0, v0.y, ay);
    }
    *(float2*)(g_agg + (size_t)warp * 64 + lane * 2) = make_float2(ax, ay);
}

// ---------------------------------------------------------------------------
// Final projection: out[i] = relu(agg[i,:] + b) . Wf + bf   (warp per node)
// ---------------------------------------------------------------------------
__global__ void final_k(const float* __restrict__ bias,
                        const float* __restrict__ Wf,
                        const float* __restrict__ bf,
                        float* __restrict__ out) {
    int g = blockIdx.x * blockDim.x + threadIdx.x;
    int node = g >> 5;
    int lane = g & 31;
    if (node >= NN) return;
    float2 a = *(const float2*)(g_agg + (size_t)node * 64 + lane * 2);
    float s = fmaxf(a.x + bias[lane * 2], 0.f) * Wf[lane * 2] +
              fmaxf(a.y + bias[lane * 2 + 1], 0.f) * Wf[lane * 2 + 1];
#pragma unroll
    for (int o = 16; o; o >>= 1) s += __shfl_xor_sync(0xFFFFFFFFu, s, o);
    if (lane == 0) out[node] = s + bf[0];
}

// ---------------------------------------------------------------------------
extern "C" void kernel_launch(void* const* d_in, const int* in_sizes, int n_in,
                              void* d_out, int out_size) {
    const float* x   = (const float*)d_in[0];
    const int*   ei  = (const int*)d_in[1];    // [2, E] int32 (JAX x64 disabled)
    const float* ew  = (const float*)d_in[2];
    const float* Ws  = (const float*)d_in[3];  // [3, 64, 64]
    const float* bs  = (const float*)d_in[4];  // [3, 64]
    const float* Wf  = (const float*)d_in[5];  // [64, 1]
    const float* bf  = (const float*)d_in[6];
    float*       out = (float*)d_out;

    const int* rows = ei;        // source nodes
    const int* cols = ei + EE;   // target nodes

    const int TB = 256;
    const int gemm_blocks = (NN + 31) / 32;
    const int node_warp_blocks = (NN * 32 + TB - 1) / TB;

    // --- CSR build + gcn_norm (once; reused across layers) ---
    init_k<<<(NN + TB - 1) / TB, TB>>>();
    count_k<<<(EE + TB - 1) / TB, TB>>>(cols, ew);
    scan_k<<<1, 1024>>>();
    rsqrt_k<<<(NN + TB - 1) / TB, TB>>>();
    fill_k<<<(EE + TB - 1) / TB, TB>>>(rows, cols, ew);

    // --- layer 0 ---
    gemm_k<<<gemm_blocks, 128>>>(x, Ws, nullptr);
    gather_k<<<node_warp_blocks, TB>>>();

    // --- layer 1 (bias0+relu fused into GEMM input read of g_agg) ---
    gemm_k<<<gemm_blocks, 128>>>(nullptr, Ws + 64 * 64, bs);
    gather_k<<<node_warp_blocks, TB>>>();

    // --- layer 2 ---
    gemm_k<<<gemm_blocks, 128>>>(nullptr, Ws + 2 * 64 * 64, bs + 64);
    gather_k<<<node_warp_blocks, TB>>>();

    // --- final projection (bias2+relu fused) ---
    final_k<<<node_warp_blocks, TB>>>(bs + 128, Wf, bf, out);
}